// round 13
// baseline (speedup 1.0000x reference)
#include <cuda_runtime.h>

#define B_    128
#define N_    4096
#define C_    768
#define H_    768
#define NC_   1000
#define TOPK_ 16
#define M_    (B_*TOPK_)   // 2048

// Scratch (static device globals — allocation-free per harness rules)
__device__ float g_xg[M_*C_];     // gathered x_topk [2048][768]
__device__ float g_score[M_];     // attention pre-softmax scores
__device__ float g_z[B_*C_];      // pooled features [128][768]
__device__ float g_h0[H_*M_];     // pool partial (K half 0), col-major [768][2048]
__device__ float g_h1[H_*M_];     // pool partial (K half 1), col-major [768][2048]

__device__ __forceinline__ unsigned long long fma2(unsigned long long a,
                                                   unsigned long long b,
                                                   unsigned long long c) {
    unsigned long long d;
    asm("fma.rn.f32x2 %0, %1, %2, %3;" : "=l"(d) : "l"(a), "l"(b), "l"(c));
    return d;
}

// ---------------------------------------------------------------------------
// Kernel 1: per-batch top-16 of r + gather x rows + zero score buffer
// ---------------------------------------------------------------------------
__global__ __launch_bounds__(256) void topk_gather_kernel(
    const float* __restrict__ x, const float* __restrict__ r)
{
    __shared__ float sr[N_];
    __shared__ float rv[256];
    __shared__ int   ri[256];
    __shared__ int   sidx[TOPK_];

    const int b   = blockIdx.x;
    const int tid = threadIdx.x;

    const float* rrow = r + (size_t)b * N_;
    for (int i = tid; i < N_; i += 256) sr[i] = rrow[i];
    __syncthreads();

    for (int it = 0; it < TOPK_; ++it) {
        float bv = -1e30f; int bi = 0;
        for (int i = tid; i < N_; i += 256) {
            float v = sr[i];
            if (v > bv) { bv = v; bi = i; }
        }
        rv[tid] = bv; ri[tid] = bi;
        __syncthreads();
        for (int s = 128; s > 0; s >>= 1) {
            if (tid < s) {
                float v2 = rv[tid + s];
                if (v2 > rv[tid] || (v2 == rv[tid] && ri[tid + s] < ri[tid])) {
                    rv[tid] = v2; ri[tid] = ri[tid + s];
                }
            }
            __syncthreads();
        }
        if (tid == 0) {
            sidx[it] = ri[0];
            sr[ri[0]] = -1e30f;   // mask out the winner
        }
        __syncthreads();
    }

    if (tid < TOPK_) g_score[b * TOPK_ + tid] = 0.0f;

    // Gather the 16 selected rows (float4, coalesced)
    for (int lin = tid; lin < TOPK_ * (C_ / 4); lin += 256) {
        int k  = lin / (C_ / 4);
        int c4 = lin % (C_ / 4);
        float4 v = ((const float4*)(x + ((size_t)b * N_ + sidx[k]) * C_))[c4];
        ((float4*)(g_xg + (size_t)(b * TOPK_ + k) * C_))[c4] = v;
    }
}

// ---------------------------------------------------------------------------
// Kernel 2: pool GEMM partials, K-SPLIT 2.  Tile 64x64, Kchunk=32, 4x4/thread
// (proven shape + swizzle + STS.128 + double-buffer).  Each z-split covers
// K=384 and stores raw fp32x2 partials col-major into g_h0 / g_h1.
// Grid (12, 32, 2) = 768 blocks -> ~8 warps/SMSP for latency hiding.
// ---------------------------------------------------------------------------
#define KB  32
#define SA  68                 // As row stride (floats)
#define SBD 132                // value-duplicated B row stride (floats)
#define KSPLIT_LEN (C_ / 2)    // 384
#define NCHUNK (KSPLIT_LEN / KB)   // 12
#define AS_BUF (KB * SA)       // 2176 floats per A stage
#define BD_BUF (KB * SBD)      // 4224 floats per B stage
#define POOL_SMEM ((2*AS_BUF + 2*BD_BUF) * 4)   // 51200 bytes

__global__ __launch_bounds__(256) void pool_kernel(const float* __restrict__ W)
{
    extern __shared__ float smem[];
    float* Asm = smem;                     // [2][KB][SA]
    float* Bdm = smem + 2 * AS_BUF;        // [2][KB][SBD]

    const int tid = threadIdx.x;
    const int n0  = blockIdx.x * 64;
    const int m0  = blockIdx.y * 64;
    const int kz0 = blockIdx.z * KSPLIT_LEN;
    float* hout = blockIdx.z ? g_h1 : g_h0;

    unsigned long long acc[2][4];
    #pragma unroll
    for (int i = 0; i < 2; ++i)
        #pragma unroll
        for (int j = 0; j < 4; ++j) acc[i][j] = 0ull;

    const int rm = (tid & 15) * 4;   // 4 consecutive M rows
    const int cn = (tid >> 4) * 4;   // 4 consecutive N cols

    // staging index precompute (proven layout)
    const int jA  = tid & 7;          // k-group (kv = 4*jA)
    const int mA0 = tid >> 3;         // m for it=0 (0..31)
    const int mA1 = mA0 + 32;         // m for it=1
    const int kvA = jA * 4;
    const int sac0 = mA0 ^ (4 * jA);  // swizzled column, it=0
    const int sac1 = mA1 ^ (4 * jA);  // swizzled column, it=1
    const int kB0 = tid >> 4;         // B k for it=0 (0..15)
    const int kB1 = kB0 + 16;         // B k for it=1
    const int n4B = (tid & 15) * 4;

    const float* pa0 = g_xg + (size_t)(m0 + mA0) * C_ + kz0 + kvA;
    const float* pa1 = g_xg + (size_t)(m0 + mA1) * C_ + kz0 + kvA;
    const float* pb0 = W + (size_t)(kz0 + kB0) * H_ + n0 + n4B;
    const float* pb1 = W + (size_t)(kz0 + kB1) * H_ + n0 + n4B;

    // preload chunk 0 into registers
    float4 ra0 = *(const float4*)pa0; pa0 += KB;
    float4 ra1 = *(const float4*)pa1; pa1 += KB;
    float4 rb0 = *(const float4*)pb0; pb0 += (size_t)KB * H_;
    float4 rb1 = *(const float4*)pb1; pb1 += (size_t)KB * H_;

    // stage chunk 0 into buffer 0
    {
        float* Aw = Asm;
        float* Bw = Bdm;
        Aw[(kvA + 0) * SA + sac0] = ra0.x;
        Aw[(kvA + 1) * SA + sac0] = ra0.y;
        Aw[(kvA + 2) * SA + sac0] = ra0.z;
        Aw[(kvA + 3) * SA + sac0] = ra0.w;
        Aw[(kvA + 0) * SA + sac1] = ra1.x;
        Aw[(kvA + 1) * SA + sac1] = ra1.y;
        Aw[(kvA + 2) * SA + sac1] = ra1.z;
        Aw[(kvA + 3) * SA + sac1] = ra1.w;
        float4 d0; d0.x = rb0.x; d0.y = rb0.x; d0.z = rb0.y; d0.w = rb0.y;
        float4 d1; d1.x = rb0.z; d1.y = rb0.z; d1.z = rb0.w; d1.w = rb0.w;
        *(float4*)&Bw[kB0 * SBD + 2 * n4B]     = d0;
        *(float4*)&Bw[kB0 * SBD + 2 * n4B + 4] = d1;
        float4 d2; d2.x = rb1.x; d2.y = rb1.x; d2.z = rb1.y; d2.w = rb1.y;
        float4 d3; d3.x = rb1.z; d3.y = rb1.z; d3.z = rb1.w; d3.w = rb1.w;
        *(float4*)&Bw[kB1 * SBD + 2 * n4B]     = d2;
        *(float4*)&Bw[kB1 * SBD + 2 * n4B + 4] = d3;
    }
    __syncthreads();

    for (int c = 0; c < NCHUNK; ++c) {
        const int buf = c & 1;
        const float* Ar = Asm + buf * AS_BUF;
        const float* Br = Bdm + buf * BD_BUF;

        if (c < NCHUNK - 1) {
            ra0 = *(const float4*)pa0; pa0 += KB;
            ra1 = *(const float4*)pa1; pa1 += KB;
            rb0 = *(const float4*)pb0; pb0 += (size_t)KB * H_;
            rb1 = *(const float4*)pb1; pb1 += (size_t)KB * H_;
        }

        #pragma unroll
        for (int kk = 0; kk < KB; ++kk) {
            const int S = 4 * ((kk >> 2) & 7);
            ulonglong2 a01 = *(const ulonglong2*)&Ar[kk * SA + (rm ^ S)];
            ulonglong2 b01 = *(const ulonglong2*)&Br[kk * SBD + 2 * cn];
            ulonglong2 b23 = *(const ulonglong2*)&Br[kk * SBD + 2 * cn + 4];
            acc[0][0] = fma2(a01.x, b01.x, acc[0][0]);
            acc[0][1] = fma2(a01.x, b01.y, acc[0][1]);
            acc[0][2] = fma2(a01.x, b23.x, acc[0][2]);
            acc[0][3] = fma2(a01.x, b23.y, acc[0][3]);
            acc[1][0] = fma2(a01.y, b01.x, acc[1][0]);
            acc[1][1] = fma2(a01.y, b01.y, acc[1][1]);
            acc[1][2] = fma2(a01.y, b23.x, acc[1][2]);
            acc[1][3] = fma2(a01.y, b23.y, acc[1][3]);
        }

        if (c < NCHUNK - 1) {
            float* Aw = Asm + (1 - buf) * AS_BUF;
            float* Bw = Bdm + (1 - buf) * BD_BUF;
            Aw[(kvA + 0) * SA + sac0] = ra0.x;
            Aw[(kvA + 1) * SA + sac0] = ra0.y;
            Aw[(kvA + 2) * SA + sac0] = ra0.z;
            Aw[(kvA + 3) * SA + sac0] = ra0.w;
            Aw[(kvA + 0) * SA + sac1] = ra1.x;
            Aw[(kvA + 1) * SA + sac1] = ra1.y;
            Aw[(kvA + 2) * SA + sac1] = ra1.z;
            Aw[(kvA + 3) * SA + sac1] = ra1.w;
            float4 d0; d0.x = rb0.x; d0.y = rb0.x; d0.z = rb0.y; d0.w = rb0.y;
            float4 d1; d1.x = rb0.z; d1.y = rb0.z; d1.z = rb0.w; d1.w = rb0.w;
            *(float4*)&Bw[kB0 * SBD + 2 * n4B]     = d0;
            *(float4*)&Bw[kB0 * SBD + 2 * n4B + 4] = d1;
            float4 d2; d2.x = rb1.x; d2.y = rb1.x; d2.z = rb1.y; d2.w = rb1.y;
            float4 d3; d3.x = rb1.z; d3.y = rb1.z; d3.z = rb1.w; d3.w = rb1.w;
            *(float4*)&Bw[kB1 * SBD + 2 * n4B]     = d2;
            *(float4*)&Bw[kB1 * SBD + 2 * n4B + 4] = d3;
            __syncthreads();
        }
    }

    // Store raw partials col-major: g_h[col][row], f32x2 STG.64, coalesced.
    #pragma unroll
    for (int n = 0; n < 4; ++n) {
        int col = n0 + cn + n;
        unsigned long long* p = (unsigned long long*)&hout[(size_t)col * M_ + m0 + rm];
        p[0] = acc[0][n];     // rows rm, rm+1
        p[1] = acc[1][n];     // rows rm+2, rm+3
    }
}

// ---------------------------------------------------------------------------
// Kernel 2b: epilogue  score[r] += sum_c tanh(h0+h1+Wb[c]) * v[c]
// Grid (8 row-blocks x 12 col-blocks), 256 threads; coalesced row-major lanes.
// ---------------------------------------------------------------------------
__global__ __launch_bounds__(256) void pool_epi_kernel(
    const float* __restrict__ Wb, const float* __restrict__ v)
{
    const int row = blockIdx.x * 256 + threadIdx.x;   // 0..2047
    const int c0  = blockIdx.y * 64;

    float s = 0.0f;
    #pragma unroll 4
    for (int c = 0; c < 64; ++c) {
        int col = c0 + c;
        float h = g_h0[(size_t)col * M_ + row] + g_h1[(size_t)col * M_ + row];
        s += tanhf(h + __ldg(&Wb[col])) * __ldg(&v[col]);
    }
    atomicAdd(&g_score[row], s);
}

// ---------------------------------------------------------------------------
// Kernel 3: softmax over 16 scores per batch + z = sum_k alpha_k * x_topk
//           + initialize output row with fc bias (fc kernel accumulates).
// ---------------------------------------------------------------------------
__global__ __launch_bounds__(256) void finalize_kernel(
    float* __restrict__ out, const float* __restrict__ fcb)
{
    const int b   = blockIdx.x;
    const int tid = threadIdx.x;
    __shared__ float sc[TOPK_];
    if (tid < TOPK_) sc[tid] = g_score[b * TOPK_ + tid];
    __syncthreads();

    float m = -1e30f;
    #pragma unroll
    for (int k = 0; k < TOPK_; ++k) m = fmaxf(m, sc[k]);
    float w[TOPK_];
    float s = 0.0f;
    #pragma unroll
    for (int k = 0; k < TOPK_; ++k) { w[k] = expf(sc[k] - m); s += w[k]; }
    float inv = 1.0f / s;
    #pragma unroll
    for (int k = 0; k < TOPK_; ++k) w[k] *= inv;

    for (int c = tid; c < C_; c += 256) {
        float z = 0.0f;
        #pragma unroll
        for (int k = 0; k < TOPK_; ++k)
            z += w[k] * g_xg[(size_t)(b * TOPK_ + k) * C_ + c];
        g_z[(size_t)b * C_ + c] = z;
    }

    // out row = fc bias; fc_kernel atomically adds z @ fc_w on top
    for (int i = tid; i < NC_; i += 256) out[(size_t)b * NC_ + i] = fcb[i];
}

// ---------------------------------------------------------------------------
// Kernel 4: fc GEMM logits += z @ fc_w.  M=128, N=1000, K=768.
// Tile 64x64, K-split 12x64 (measured best), register prefetch of chunk 1.
// ---------------------------------------------------------------------------
#define SAF 68
#define SBF 132

__global__ __launch_bounds__(256) void fc_kernel(
    const float* __restrict__ fcw, float* __restrict__ out)
{
    __shared__ float As[KB][SAF];
    __shared__ float Bd[KB][SBF];

    const int tid = threadIdx.x;
    const int n0  = blockIdx.x * 64;
    const int m0  = blockIdx.y * 64;
    const int kz0 = blockIdx.z * 64;

    unsigned long long acc[2][4];
    #pragma unroll
    for (int i = 0; i < 2; ++i)
        #pragma unroll
        for (int j = 0; j < 4; ++j) acc[i][j] = 0ull;

    const int rm = (tid & 15) * 4;
    const int cn = (tid >> 4) * 4;

    const int mA0 = tid >> 3;         // 0..31
    const int mA1 = mA0 + 32;
    const int kvA = (tid & 7) * 4;
    const int kB0 = tid >> 4;         // 0..15
    const int kB1 = kB0 + 16;
    const int n4B = (tid & 15) * 4;
    const int colB = n0 + n4B;

    // load chunk 0 regs
    float4 ca0 = *(const float4*)(g_z + (size_t)(m0 + mA0) * C_ + kz0 + kvA);
    float4 ca1 = *(const float4*)(g_z + (size_t)(m0 + mA1) * C_ + kz0 + kvA);
    float4 cb0 = (colB < NC_) ? *(const float4*)(fcw + (size_t)(kz0 + kB0) * NC_ + colB)
                              : make_float4(0.f, 0.f, 0.f, 0.f);
    float4 cb1 = (colB < NC_) ? *(const float4*)(fcw + (size_t)(kz0 + kB1) * NC_ + colB)
                              : make_float4(0.f, 0.f, 0.f, 0.f);

    #pragma unroll
    for (int half = 0; half < 2; ++half) {
        As[kvA + 0][mA0] = ca0.x; As[kvA + 1][mA0] = ca0.y;
        As[kvA + 2][mA0] = ca0.z; As[kvA + 3][mA0] = ca0.w;
        As[kvA + 0][mA1] = ca1.x; As[kvA + 1][mA1] = ca1.y;
        As[kvA + 2][mA1] = ca1.z; As[kvA + 3][mA1] = ca1.w;
        {
            float* p = &Bd[kB0][2 * n4B];
            p[0] = cb0.x; p[1] = cb0.x; p[2] = cb0.y; p[3] = cb0.y;
            p[4] = cb0.z; p[5] = cb0.z; p[6] = cb0.w; p[7] = cb0.w;
            float* q = &Bd[kB1][2 * n4B];
            q[0] = cb1.x; q[1] = cb1.x; q[2] = cb1.y; q[3] = cb1.y;
            q[4] = cb1.z; q[5] = cb1.z; q[6] = cb1.w; q[7] = cb1.w;
        }
        __syncthreads();

        if (half == 0) {
            int k0n = kz0 + 32;
            ca0 = *(const float4*)(g_z + (size_t)(m0 + mA0) * C_ + k0n + kvA);
            ca1 = *(const float4*)(g_z + (size_t)(m0 + mA1) * C_ + k0n + kvA);
            cb0 = (colB < NC_) ? *(const float4*)(fcw + (size_t)(k0n + kB0) * NC_ + colB)
                               : make_float4(0.f, 0.f, 0.f, 0.f);
            cb1 = (colB < NC_) ? *(const float4*)(fcw + (size_t)(k0n + kB1) * NC_ + colB)
                               : make_float4(0.f, 0.f, 0.f, 0.f);
        }

        #pragma unroll 8
        for (int kk = 0; kk < KB; ++kk) {
            ulonglong2 a01 = *(const ulonglong2*)&As[kk][rm];
            ulonglong2 b01 = *(const ulonglong2*)&Bd[kk][2 * cn];
            ulonglong2 b23 = *(const ulonglong2*)&Bd[kk][2 * cn + 4];
            acc[0][0] = fma2(a01.x, b01.x, acc[0][0]);
            acc[0][1] = fma2(a01.x, b01.y, acc[0][1]);
            acc[0][2] = fma2(a01.x, b23.x, acc[0][2]);
            acc[0][3] = fma2(a01.x, b23.y, acc[0][3]);
            acc[1][0] = fma2(a01.y, b01.x, acc[1][0]);
            acc[1][1] = fma2(a01.y, b01.y, acc[1][1]);
            acc[1][2] = fma2(a01.y, b23.x, acc[1][2]);
            acc[1][3] = fma2(a01.y, b23.y, acc[1][3]);
        }
        if (half == 0) __syncthreads();
    }

    #pragma unroll
    for (int n = 0; n < 4; ++n) {
        int col = n0 + cn + n;
        if (col < NC_) {
            #pragma unroll
            for (int mp = 0; mp < 2; ++mp) {
                unsigned long long a = acc[mp][n];
                float lo = __uint_as_float((unsigned)(a & 0xffffffffull));
                float hi = __uint_as_float((unsigned)(a >> 32));
                int row0 = m0 + rm + 2 * mp;
                atomicAdd(&out[(size_t)row0 * NC_ + col], lo);
                atomicAdd(&out[(size_t)(row0 + 1) * NC_ + col], hi);
            }
        }
    }
}

// ---------------------------------------------------------------------------
extern "C" void kernel_launch(void* const* d_in, const int* in_sizes, int n_in,
                              void* d_out, int out_size)
{
    const float* x   = (const float*)d_in[0];
    const float* r   = (const float*)d_in[1];
    const float* pWw = (const float*)d_in[2];
    const float* pWb = (const float*)d_in[3];
    const float* pvw = (const float*)d_in[4];
    // d_in[5] = pool_v_b: constant shift before softmax -> cancels, unused
    const float* fcw = (const float*)d_in[6];
    const float* fcb = (const float*)d_in[7];
    float* out = (float*)d_out;

    cudaFuncSetAttribute(pool_kernel,
                         cudaFuncAttributeMaxDynamicSharedMemorySize, POOL_SMEM);

    topk_gather_kernel<<<B_, 256>>>(x, r);
    pool_kernel<<<dim3(H_ / 64, M_ / 64, 2), 256, POOL_SMEM>>>(pWw);  // 768 blocks
    pool_epi_kernel<<<dim3(M_ / 256, H_ / 64), 256>>>(pWb, pvw);      // (8,12)
    finalize_kernel<<<B_, 256>>>(out, fcb);
    fc_kernel<<<dim3(16, 2, 12), 256>>>(fcw, out);
}

// round 14
// speedup vs baseline: 1.1311x; 1.1311x over previous
#include <cuda_runtime.h>

#define B_    128
#define N_    4096
#define C_    768
#define H_    768
#define NC_   1000
#define TOPK_ 16
#define M_    (B_*TOPK_)   // 2048

// Scratch (static device globals — allocation-free per harness rules)
__device__ float g_xg[M_*C_];     // gathered x_topk [2048][768]
__device__ float g_score[M_];     // attention pre-softmax scores
__device__ float g_z[B_*C_];      // pooled features [128][768]

__device__ __forceinline__ unsigned long long fma2(unsigned long long a,
                                                   unsigned long long b,
                                                   unsigned long long c) {
    unsigned long long d;
    asm("fma.rn.f32x2 %0, %1, %2, %3;" : "=l"(d) : "l"(a), "l"(b), "l"(c));
    return d;
}

// ---------------------------------------------------------------------------
// Kernel 1: per-batch top-16 of r + gather x rows + zero score buffer.
// Warp-shuffle reduce: 2 block barriers per iteration (was 9).
// ---------------------------------------------------------------------------
__global__ __launch_bounds__(256) void topk_gather_kernel(
    const float* __restrict__ x, const float* __restrict__ r)
{
    __shared__ float sr[N_];
    __shared__ float rv[8];
    __shared__ int   ri[8];
    __shared__ int   sidx[TOPK_];

    const int b   = blockIdx.x;
    const int tid = threadIdx.x;
    const int wid = tid >> 5;
    const int lid = tid & 31;

    const float* rrow = r + (size_t)b * N_;
    for (int i = tid; i < N_; i += 256) sr[i] = rrow[i];
    __syncthreads();

    for (int it = 0; it < TOPK_; ++it) {
        float bv = -1e30f; int bi = 0;
        for (int i = tid; i < N_; i += 256) {
            float v = sr[i];
            if (v > bv) { bv = v; bi = i; }
        }
        // in-warp reduce (no barriers)
        #pragma unroll
        for (int s = 16; s > 0; s >>= 1) {
            float ov = __shfl_down_sync(0xffffffffu, bv, s);
            int   oi = __shfl_down_sync(0xffffffffu, bi, s);
            if (ov > bv || (ov == bv && oi < bi)) { bv = ov; bi = oi; }
        }
        if (lid == 0) { rv[wid] = bv; ri[wid] = bi; }
        __syncthreads();
        if (tid == 0) {
            float wv = rv[0]; int wi = ri[0];
            #pragma unroll
            for (int q = 1; q < 8; ++q) {
                if (rv[q] > wv || (rv[q] == wv && ri[q] < wi)) { wv = rv[q]; wi = ri[q]; }
            }
            sidx[it] = wi;
            sr[wi] = -1e30f;   // mask out the winner
        }
        __syncthreads();
    }

    if (tid < TOPK_) g_score[b * TOPK_ + tid] = 0.0f;

    // Gather the 16 selected rows (float4, coalesced)
    for (int lin = tid; lin < TOPK_ * (C_ / 4); lin += 256) {
        int k  = lin / (C_ / 4);
        int c4 = lin % (C_ / 4);
        float4 v = ((const float4*)(x + ((size_t)b * N_ + sidx[k]) * C_))[c4];
        ((float4*)(g_xg + (size_t)(b * TOPK_ + k) * C_))[c4] = v;
    }
}

// ---------------------------------------------------------------------------
// Kernel 2: pool GEMM  h = tanh(Xg @ W + b),  score += h . v   (fused)
// M=2048, N=768, K=768.  Tile 64x64, Kchunk=32, 4x4/thread, swizzled A,
// STS.128 B, smem double-buffered.  (Round-12 proven, byte-frozen.)
// ---------------------------------------------------------------------------
#define KB  32
#define SA  68                 // As row stride (floats)
#define SBD 132                // value-duplicated B row stride (floats)
#define NCHUNK (C_ / KB)       // 24
#define AS_BUF (KB * SA)       // 2176 floats per A stage
#define BD_BUF (KB * SBD)      // 4224 floats per B stage
#define POOL_SMEM ((2*AS_BUF + 2*BD_BUF + 64) * 4)   // 51456 bytes

__global__ __launch_bounds__(256) void pool_kernel(
    const float* __restrict__ W, const float* __restrict__ Wb,
    const float* __restrict__ v)
{
    extern __shared__ float smem[];
    float* Asm = smem;                     // [2][KB][SA]
    float* Bdm = smem + 2 * AS_BUF;        // [2][KB][SBD]
    float* bs  = smem + 2 * AS_BUF + 2 * BD_BUF;   // [64]

    const int tid = threadIdx.x;
    const int n0  = blockIdx.x * 64;
    const int m0  = blockIdx.y * 64;

    if (tid < 64) bs[tid] = 0.0f;

    unsigned long long acc[2][4];
    #pragma unroll
    for (int i = 0; i < 2; ++i)
        #pragma unroll
        for (int j = 0; j < 4; ++j) acc[i][j] = 0ull;

    const int rm = (tid & 15) * 4;   // 4 consecutive M rows
    const int cn = (tid >> 4) * 4;   // 4 consecutive N cols

    const int jA  = tid & 7;          // k-group (kv = 4*jA)
    const int mA0 = tid >> 3;         // m for it=0 (0..31)
    const int mA1 = mA0 + 32;         // m for it=1
    const int kvA = jA * 4;
    const int sac0 = mA0 ^ (4 * jA);  // swizzled column, it=0
    const int sac1 = mA1 ^ (4 * jA);  // swizzled column, it=1
    const int kB0 = tid >> 4;         // B k for it=0 (0..15)
    const int kB1 = kB0 + 16;         // B k for it=1
    const int n4B = (tid & 15) * 4;

    const float* pa0 = g_xg + (size_t)(m0 + mA0) * C_ + kvA;
    const float* pa1 = g_xg + (size_t)(m0 + mA1) * C_ + kvA;
    const float* pb0 = W + (size_t)kB0 * H_ + n0 + n4B;
    const float* pb1 = W + (size_t)kB1 * H_ + n0 + n4B;

    float4 ra0 = *(const float4*)pa0; pa0 += KB;
    float4 ra1 = *(const float4*)pa1; pa1 += KB;
    float4 rb0 = *(const float4*)pb0; pb0 += (size_t)KB * H_;
    float4 rb1 = *(const float4*)pb1; pb1 += (size_t)KB * H_;

    {
        float* Aw = Asm;
        float* Bw = Bdm;
        Aw[(kvA + 0) * SA + sac0] = ra0.x;
        Aw[(kvA + 1) * SA + sac0] = ra0.y;
        Aw[(kvA + 2) * SA + sac0] = ra0.z;
        Aw[(kvA + 3) * SA + sac0] = ra0.w;
        Aw[(kvA + 0) * SA + sac1] = ra1.x;
        Aw[(kvA + 1) * SA + sac1] = ra1.y;
        Aw[(kvA + 2) * SA + sac1] = ra1.z;
        Aw[(kvA + 3) * SA + sac1] = ra1.w;
        float4 d0; d0.x = rb0.x; d0.y = rb0.x; d0.z = rb0.y; d0.w = rb0.y;
        float4 d1; d1.x = rb0.z; d1.y = rb0.z; d1.z = rb0.w; d1.w = rb0.w;
        *(float4*)&Bw[kB0 * SBD + 2 * n4B]     = d0;
        *(float4*)&Bw[kB0 * SBD + 2 * n4B + 4] = d1;
        float4 d2; d2.x = rb1.x; d2.y = rb1.x; d2.z = rb1.y; d2.w = rb1.y;
        float4 d3; d3.x = rb1.z; d3.y = rb1.z; d3.z = rb1.w; d3.w = rb1.w;
        *(float4*)&Bw[kB1 * SBD + 2 * n4B]     = d2;
        *(float4*)&Bw[kB1 * SBD + 2 * n4B + 4] = d3;
    }
    __syncthreads();

    for (int c = 0; c < NCHUNK; ++c) {
        const int buf = c & 1;
        const float* Ar = Asm + buf * AS_BUF;
        const float* Br = Bdm + buf * BD_BUF;

        if (c < NCHUNK - 1) {
            ra0 = *(const float4*)pa0; pa0 += KB;
            ra1 = *(const float4*)pa1; pa1 += KB;
            rb0 = *(const float4*)pb0; pb0 += (size_t)KB * H_;
            rb1 = *(const float4*)pb1; pb1 += (size_t)KB * H_;
        }

        #pragma unroll
        for (int kk = 0; kk < KB; ++kk) {
            const int S = 4 * ((kk >> 2) & 7);
            ulonglong2 a01 = *(const ulonglong2*)&Ar[kk * SA + (rm ^ S)];
            ulonglong2 b01 = *(const ulonglong2*)&Br[kk * SBD + 2 * cn];
            ulonglong2 b23 = *(const ulonglong2*)&Br[kk * SBD + 2 * cn + 4];
            acc[0][0] = fma2(a01.x, b01.x, acc[0][0]);
            acc[0][1] = fma2(a01.x, b01.y, acc[0][1]);
            acc[0][2] = fma2(a01.x, b23.x, acc[0][2]);
            acc[0][3] = fma2(a01.x, b23.y, acc[0][3]);
            acc[1][0] = fma2(a01.y, b01.x, acc[1][0]);
            acc[1][1] = fma2(a01.y, b01.y, acc[1][1]);
            acc[1][2] = fma2(a01.y, b23.x, acc[1][2]);
            acc[1][3] = fma2(a01.y, b23.y, acc[1][3]);
        }

        if (c < NCHUNK - 1) {
            float* Aw = Asm + (1 - buf) * AS_BUF;
            float* Bw = Bdm + (1 - buf) * BD_BUF;
            Aw[(kvA + 0) * SA + sac0] = ra0.x;
            Aw[(kvA + 1) * SA + sac0] = ra0.y;
            Aw[(kvA + 2) * SA + sac0] = ra0.z;
            Aw[(kvA + 3) * SA + sac0] = ra0.w;
            Aw[(kvA + 0) * SA + sac1] = ra1.x;
            Aw[(kvA + 1) * SA + sac1] = ra1.y;
            Aw[(kvA + 2) * SA + sac1] = ra1.z;
            Aw[(kvA + 3) * SA + sac1] = ra1.w;
            float4 d0; d0.x = rb0.x; d0.y = rb0.x; d0.z = rb0.y; d0.w = rb0.y;
            float4 d1; d1.x = rb0.z; d1.y = rb0.z; d1.z = rb0.w; d1.w = rb0.w;
            *(float4*)&Bw[kB0 * SBD + 2 * n4B]     = d0;
            *(float4*)&Bw[kB0 * SBD + 2 * n4B + 4] = d1;
            float4 d2; d2.x = rb1.x; d2.y = rb1.x; d2.z = rb1.y; d2.w = rb1.y;
            float4 d3; d3.x = rb1.z; d3.y = rb1.z; d3.z = rb1.w; d3.w = rb1.w;
            *(float4*)&Bw[kB1 * SBD + 2 * n4B]     = d2;
            *(float4*)&Bw[kB1 * SBD + 2 * n4B + 4] = d3;
            __syncthreads();
        }
    }

    // Epilogue: tanh + dot with v, reduce per-row
    float sp[4] = {0.f, 0.f, 0.f, 0.f};
    #pragma unroll
    for (int n = 0; n < 4; ++n) {
        int col  = n0 + cn + n;
        float wb = Wb[col];
        float vv = v[col];
        #pragma unroll
        for (int mp = 0; mp < 2; ++mp) {
            unsigned long long a = acc[mp][n];
            float lo = __uint_as_float((unsigned)(a & 0xffffffffull));
            float hi = __uint_as_float((unsigned)(a >> 32));
            sp[2 * mp + 0] += tanhf(lo + wb) * vv;
            sp[2 * mp + 1] += tanhf(hi + wb) * vv;
        }
    }
    #pragma unroll
    for (int j = 0; j < 4; ++j) atomicAdd(&bs[rm + j], sp[j]);
    __syncthreads();
    if (tid < 64) atomicAdd(&g_score[m0 + tid], bs[tid]);
}

// ---------------------------------------------------------------------------
// Kernel 3: softmax(16) + z + bias init, COLUMN-SPLIT x3 for bandwidth.
// Grid (128, 3): block (b, cb) handles z cols [cb*256, cb*256+256) and
// bias cols [cb*334, min(cb*334+334, 1000)).
// ---------------------------------------------------------------------------
__global__ __launch_bounds__(256) void finalize_kernel(
    float* __restrict__ out, const float* __restrict__ fcb)
{
    const int b   = blockIdx.x;
    const int cb  = blockIdx.y;
    const int tid = threadIdx.x;
    __shared__ float sc[TOPK_];
    if (tid < TOPK_) sc[tid] = g_score[b * TOPK_ + tid];
    __syncthreads();

    float m = -1e30f;
    #pragma unroll
    for (int k = 0; k < TOPK_; ++k) m = fmaxf(m, sc[k]);
    float w[TOPK_];
    float s = 0.0f;
    #pragma unroll
    for (int k = 0; k < TOPK_; ++k) { w[k] = expf(sc[k] - m); s += w[k]; }
    float inv = 1.0f / s;
    #pragma unroll
    for (int k = 0; k < TOPK_; ++k) w[k] *= inv;

    // 256 z-columns for this block: one per thread
    {
        int c = cb * 256 + tid;
        float z = 0.0f;
        #pragma unroll
        for (int k = 0; k < TOPK_; ++k)
            z += w[k] * g_xg[(size_t)(b * TOPK_ + k) * C_ + c];
        g_z[(size_t)b * C_ + c] = z;
    }

    // bias third: out row = fc bias; fc_kernel atomically adds on top
    int i0 = cb * 334;
    int i1 = i0 + 334; if (i1 > NC_) i1 = NC_;
    for (int i = i0 + tid; i < i1; i += 256) out[(size_t)b * NC_ + i] = fcb[i];
}

// ---------------------------------------------------------------------------
// Kernel 4: fc GEMM logits += z @ fc_w.  M=128, N=1000, K=768.
// Tile 64x64, K-split 12x64 (measured best), register prefetch of chunk 1.
// (Round-12 proven, byte-frozen.)
// ---------------------------------------------------------------------------
#define SAF 68
#define SBF 132

__global__ __launch_bounds__(256) void fc_kernel(
    const float* __restrict__ fcw, float* __restrict__ out)
{
    __shared__ float As[KB][SAF];
    __shared__ float Bd[KB][SBF];

    const int tid = threadIdx.x;
    const int n0  = blockIdx.x * 64;
    const int m0  = blockIdx.y * 64;
    const int kz0 = blockIdx.z * 64;

    unsigned long long acc[2][4];
    #pragma unroll
    for (int i = 0; i < 2; ++i)
        #pragma unroll
        for (int j = 0; j < 4; ++j) acc[i][j] = 0ull;

    const int rm = (tid & 15) * 4;
    const int cn = (tid >> 4) * 4;

    const int mA0 = tid >> 3;         // 0..31
    const int mA1 = mA0 + 32;
    const int kvA = (tid & 7) * 4;
    const int kB0 = tid >> 4;         // 0..15
    const int kB1 = kB0 + 16;
    const int n4B = (tid & 15) * 4;
    const int colB = n0 + n4B;

    float4 ca0 = *(const float4*)(g_z + (size_t)(m0 + mA0) * C_ + kz0 + kvA);
    float4 ca1 = *(const float4*)(g_z + (size_t)(m0 + mA1) * C_ + kz0 + kvA);
    float4 cb0 = (colB < NC_) ? *(const float4*)(fcw + (size_t)(kz0 + kB0) * NC_ + colB)
                              : make_float4(0.f, 0.f, 0.f, 0.f);
    float4 cb1 = (colB < NC_) ? *(const float4*)(fcw + (size_t)(kz0 + kB1) * NC_ + colB)
                              : make_float4(0.f, 0.f, 0.f, 0.f);

    #pragma unroll
    for (int half = 0; half < 2; ++half) {
        As[kvA + 0][mA0] = ca0.x; As[kvA + 1][mA0] = ca0.y;
        As[kvA + 2][mA0] = ca0.z; As[kvA + 3][mA0] = ca0.w;
        As[kvA + 0][mA1] = ca1.x; As[kvA + 1][mA1] = ca1.y;
        As[kvA + 2][mA1] = ca1.z; As[kvA + 3][mA1] = ca1.w;
        {
            float* p = &Bd[kB0][2 * n4B];
            p[0] = cb0.x; p[1] = cb0.x; p[2] = cb0.y; p[3] = cb0.y;
            p[4] = cb0.z; p[5] = cb0.z; p[6] = cb0.w; p[7] = cb0.w;
            float* q = &Bd[kB1][2 * n4B];
            q[0] = cb1.x; q[1] = cb1.x; q[2] = cb1.y; q[3] = cb1.y;
            q[4] = cb1.z; q[5] = cb1.z; q[6] = cb1.w; q[7] = cb1.w;
        }
        __syncthreads();

        if (half == 0) {
            int k0n = kz0 + 32;
            ca0 = *(const float4*)(g_z + (size_t)(m0 + mA0) * C_ + k0n + kvA);
            ca1 = *(const float4*)(g_z + (size_t)(m0 + mA1) * C_ + k0n + kvA);
            cb0 = (colB < NC_) ? *(const float4*)(fcw + (size_t)(k0n + kB0) * NC_ + colB)
                               : make_float4(0.f, 0.f, 0.f, 0.f);
            cb1 = (colB < NC_) ? *(const float4*)(fcw + (size_t)(k0n + kB1) * NC_ + colB)
                               : make_float4(0.f, 0.f, 0.f, 0.f);
        }

        #pragma unroll 8
        for (int kk = 0; kk < KB; ++kk) {
            ulonglong2 a01 = *(const ulonglong2*)&As[kk][rm];
            ulonglong2 b01 = *(const ulonglong2*)&Bd[kk][2 * cn];
            ulonglong2 b23 = *(const ulonglong2*)&Bd[kk][2 * cn + 4];
            acc[0][0] = fma2(a01.x, b01.x, acc[0][0]);
            acc[0][1] = fma2(a01.x, b01.y, acc[0][1]);
            acc[0][2] = fma2(a01.x, b23.x, acc[0][2]);
            acc[0][3] = fma2(a01.x, b23.y, acc[0][3]);
            acc[1][0] = fma2(a01.y, b01.x, acc[1][0]);
            acc[1][1] = fma2(a01.y, b01.y, acc[1][1]);
            acc[1][2] = fma2(a01.y, b23.x, acc[1][2]);
            acc[1][3] = fma2(a01.y, b23.y, acc[1][3]);
        }
        if (half == 0) __syncthreads();
    }

    #pragma unroll
    for (int n = 0; n < 4; ++n) {
        int col = n0 + cn + n;
        if (col < NC_) {
            #pragma unroll
            for (int mp = 0; mp < 2; ++mp) {
                unsigned long long a = acc[mp][n];
                float lo = __uint_as_float((unsigned)(a & 0xffffffffull));
                float hi = __uint_as_float((unsigned)(a >> 32));
                int row0 = m0 + rm + 2 * mp;
                atomicAdd(&out[(size_t)row0 * NC_ + col], lo);
                atomicAdd(&out[(size_t)(row0 + 1) * NC_ + col], hi);
            }
        }
    }
}

// ---------------------------------------------------------------------------
extern "C" void kernel_launch(void* const* d_in, const int* in_sizes, int n_in,
                              void* d_out, int out_size)
{
    const float* x   = (const float*)d_in[0];
    const float* r   = (const float*)d_in[1];
    const float* pWw = (const float*)d_in[2];
    const float* pWb = (const float*)d_in[3];
    const float* pvw = (const float*)d_in[4];
    // d_in[5] = pool_v_b: constant shift before softmax -> cancels, unused
    const float* fcw = (const float*)d_in[6];
    const float* fcb = (const float*)d_in[7];
    float* out = (float*)d_out;

    cudaFuncSetAttribute(pool_kernel,
                         cudaFuncAttributeMaxDynamicSharedMemorySize, POOL_SMEM);

    topk_gather_kernel<<<B_, 256>>>(x, r);
    pool_kernel<<<dim3(H_ / 64, M_ / 64), 256, POOL_SMEM>>>(pWw, pWb, pvw);
    finalize_kernel<<<dim3(B_, 3), 256>>>(out, fcb);
    fc_kernel<<<dim3(16, 2, 12), 256>>>(fcw, out);
}